// round 9
// baseline (speedup 1.0000x reference)
#include <cuda_runtime.h>
#include <cuda_bf16.h>
#include <math.h>

#define B_  4
#define S_  2048
#define D_  2048
#define H_  16
#define HD_ 128
#define RD_ 64
#define QL_ 512
#define KL_ 512
#define MT  (B_*S_)
#define DK_ 576
#define SM_SCALE 0.07216878364870323f  // 1/sqrt(192)

// ------------------- scratch (device globals; no runtime allocs) ------------
__device__ float g_qc   [(size_t)MT * QL_];
__device__ float g_qnope[(size_t)MT * D_];
__device__ float g_qrope[(size_t)MT * (H_ * RD_)];
__device__ float g_krope[(size_t)MT * RD_];
__device__ float g_q576 [(size_t)H_ * MT * DK_];   // [h][m][576] tf32*scale
__device__ float g_k576 [(size_t)MT * DK_];        // [m][576] tf32
__device__ float g_score[(size_t)B_ * H_ * S_ * S_]; // [b*16+h][q][t]
__device__ float g_lat  [(size_t)H_ * MT * KL_];
__device__ float g_outhd[(size_t)MT * D_];

// ------------------- tf32 mma helpers ----------------------------------------
__device__ __forceinline__ unsigned f2tf(float f)
{
    unsigned u; asm("cvt.rna.tf32.f32 %0, %1;" : "=r"(u) : "f"(f)); return u;
}
__device__ __forceinline__ void mma_tf32(float c[4],
    unsigned a0, unsigned a1, unsigned a2, unsigned a3,
    unsigned b0, unsigned b1)
{
    asm volatile("mma.sync.aligned.m16n8k8.row.col.f32.tf32.tf32.f32 "
                 "{%0,%1,%2,%3},{%4,%5,%6,%7},{%8,%9},{%0,%1,%2,%3};"
                 : "+f"(c[0]), "+f"(c[1]), "+f"(c[2]), "+f"(c[3])
                 : "r"(a0), "r"(a1), "r"(a2), "r"(a3), "r"(b0), "r"(b1));
}

#define GKS 36
// shared mainloop body: sA/sB filled, run 32-deep k chunk
__device__ __forceinline__ void mma_block_32(
    const unsigned* sA, const unsigned* sB, float acc[2][8][4],
    int wm, int wn, int gid, int tig)
{
#pragma unroll
    for (int kk = 0; kk < 4; kk++) {
        const int k8 = kk * 8;
        unsigned a[2][4], b[8][2];
#pragma unroll
        for (int mt = 0; mt < 2; mt++) {
            const unsigned* p = sA + (wm + mt * 16 + gid) * GKS + k8 + tig;
            a[mt][0] = p[0];
            a[mt][1] = p[8 * GKS];
            a[mt][2] = p[4];
            a[mt][3] = p[8 * GKS + 4];
        }
#pragma unroll
        for (int nt = 0; nt < 8; nt++) {
            const unsigned* p = sB + (wn + nt * 8 + gid) * GKS + k8 + tig;
            b[nt][0] = p[0];
            b[nt][1] = p[4];
        }
#pragma unroll
        for (int mt = 0; mt < 2; mt++)
#pragma unroll
            for (int nt = 0; nt < 8; nt++)
                mma_tf32(acc[mt][nt], a[mt][0], a[mt][1], a[mt][2], a[mt][3],
                         b[nt][0], b[nt][1]);
    }
}

// ------------------- tf32 tensor-core GEMM (projections) ----------------------
// C[M,N] = ((A @ B(^T)) + bias) * sigmoid(gates[z]) * uscale, opt tf32-rounded.
template<bool TRANSB>
__global__ __launch_bounds__(256) void gemm_tf32(
    const float* __restrict__ A, int lda, long long sAz,
    const float* __restrict__ B, int ldb, long long sBz,
    float* __restrict__ C, int ldc, long long sCz,
    int N, int K,
    const float* __restrict__ bias,
    const float* __restrict__ gates,
    float uscale, int tf32out)
{
    __shared__ unsigned sA[128 * GKS];
    __shared__ unsigned sB[128 * GKS];

    const int z = blockIdx.z;
    A += (long long)z * sAz;  B += (long long)z * sBz;  C += (long long)z * sCz;

    const int tid = threadIdx.x;
    const int warp = tid >> 5, lane = tid & 31;
    const int gid = lane >> 2, tig = lane & 3;
    const int m0 = blockIdx.y * 128, n0 = blockIdx.x * 128;
    const int wm = (warp & 3) * 32;
    const int wn = (warp >> 2) * 64;

    float acc[2][8][4];
#pragma unroll
    for (int mt = 0; mt < 2; mt++)
#pragma unroll
        for (int nt = 0; nt < 8; nt++)
#pragma unroll
            for (int j = 0; j < 4; j++) acc[mt][nt][j] = 0.f;

    for (int k0 = 0; k0 < K; k0 += 32) {
#pragma unroll
        for (int i = 0; i < 4; i++) {
            const int lin = tid + i * 256;
            const int r = lin >> 3, c4 = (lin & 7) * 4;
            float4 v = *(const float4*)(A + (long long)(m0 + r) * lda + k0 + c4);
            unsigned* d = sA + r * GKS + c4;
            d[0] = f2tf(v.x); d[1] = f2tf(v.y); d[2] = f2tf(v.z); d[3] = f2tf(v.w);
        }
        if (TRANSB) {
#pragma unroll
            for (int i = 0; i < 4; i++) {
                const int lin = tid + i * 256;
                const int r = lin >> 3, c4 = (lin & 7) * 4;
                float4 v = make_float4(0.f, 0.f, 0.f, 0.f);
                if (n0 + r < N)
                    v = *(const float4*)(B + (long long)(n0 + r) * ldb + k0 + c4);
                unsigned* d = sB + r * GKS + c4;
                d[0] = f2tf(v.x); d[1] = f2tf(v.y); d[2] = f2tf(v.z); d[3] = f2tf(v.w);
            }
        } else {
#pragma unroll
            for (int i = 0; i < 16; i++) {
                const int lin = tid + i * 256;
                const int n = lin & 127, k = lin >> 7;
                float v = (n0 + n < N) ? B[(long long)(k0 + k) * ldb + n0 + n] : 0.f;
                sB[n * GKS + k] = f2tf(v);
            }
        }
        __syncthreads();
        mma_block_32(sA, sB, acc, wm, wn, gid, tig);
        __syncthreads();
    }

    float scale = uscale;
    if (gates) scale *= 1.f / (1.f + expf(-gates[z]));
#pragma unroll
    for (int mt = 0; mt < 2; mt++) {
        const int r0 = m0 + wm + mt * 16 + gid;
#pragma unroll
        for (int nt = 0; nt < 8; nt++) {
            const int col = n0 + wn + nt * 8 + tig * 2;
            if (col < N) {
                float bx = 0.f, by = 0.f;
                if (bias) { bx = bias[col]; by = bias[col + 1]; }
                float v00 = (acc[mt][nt][0] + bx) * scale;
                float v01 = (acc[mt][nt][1] + by) * scale;
                float v10 = (acc[mt][nt][2] + bx) * scale;
                float v11 = (acc[mt][nt][3] + by) * scale;
                if (tf32out) {
                    v00 = __uint_as_float(f2tf(v00));
                    v01 = __uint_as_float(f2tf(v01));
                    v10 = __uint_as_float(f2tf(v10));
                    v11 = __uint_as_float(f2tf(v11));
                }
                *(float2*)(C + (long long)r0 * ldc + col)       = make_float2(v00, v01);
                *(float2*)(C + (long long)(r0 + 8) * ldc + col) = make_float2(v10, v11);
            }
        }
    }
}

// ------------------- score GEMM: S = Q576 @ K576^T (causal blocks) -----------
// grid (kvtile 16, qtile 16, bh 64); block z: b = z>>4, h = z&15.
__global__ __launch_bounds__(256) void score_gemm(void)
{
    if (blockIdx.x > blockIdx.y) return;   // fully masked block
    __shared__ unsigned sA[128 * GKS];
    __shared__ unsigned sB[128 * GKS];

    const int z = blockIdx.z;
    const int b = z >> 4, h = z & 15;
    const float* A = g_q576 + ((size_t)h * MT + (size_t)b * S_) * DK_;
    const float* B = g_k576 + (size_t)b * S_ * DK_;
    float* C = g_score + (size_t)z * S_ * S_;

    const int tid = threadIdx.x;
    const int warp = tid >> 5, lane = tid & 31;
    const int gid = lane >> 2, tig = lane & 3;
    const int m0 = blockIdx.y * 128, n0 = blockIdx.x * 128;
    const int wm = (warp & 3) * 32;
    const int wn = (warp >> 2) * 64;

    float acc[2][8][4];
#pragma unroll
    for (int mt = 0; mt < 2; mt++)
#pragma unroll
        for (int nt = 0; nt < 8; nt++)
#pragma unroll
            for (int j = 0; j < 4; j++) acc[mt][nt][j] = 0.f;

    for (int k0 = 0; k0 < DK_; k0 += 32) {
#pragma unroll
        for (int i = 0; i < 4; i++) {
            const int lin = tid + i * 256;
            const int r = lin >> 3, c4 = (lin & 7) * 4;
            // inputs pre-rounded tf32: raw bit copy
            uint4 v = *(const uint4*)(A + (long long)(m0 + r) * DK_ + k0 + c4);
            *(uint4*)(sA + r * GKS + c4) = v;
            uint4 w = *(const uint4*)(B + (long long)(n0 + r) * DK_ + k0 + c4);
            *(uint4*)(sB + r * GKS + c4) = w;
        }
        __syncthreads();
        mma_block_32(sA, sB, acc, wm, wn, gid, tig);
        __syncthreads();
    }

#pragma unroll
    for (int mt = 0; mt < 2; mt++) {
        const int r0 = m0 + wm + mt * 16 + gid;
#pragma unroll
        for (int nt = 0; nt < 8; nt++) {
            const int col = n0 + wn + nt * 8 + tig * 2;
            *(float2*)(C + (size_t)r0 * S_ + col) =
                make_float2(acc[mt][nt][0], acc[mt][nt][1]);
            *(float2*)(C + (size_t)(r0 + 8) * S_ + col) =
                make_float2(acc[mt][nt][2], acc[mt][nt][3]);
        }
    }
}

// ------------------- row softmax (exact, two pass), P normalized+tf32 --------
// one warp per row; zero-fill to 128 boundary for PV.
__global__ __launch_bounds__(256) void softmax_rows(void)
{
    const int gwarp = (blockIdx.x * 256 + threadIdx.x) >> 5;
    const int lane = threadIdx.x & 31;
    const int z = gwarp >> 11;           // bh
    const int i = gwarp & (S_ - 1);      // row
    float* p = g_score + (size_t)z * S_ * S_ + (size_t)i * S_;
    const int len = i + 1;
    const int pe = ((i >> 7) + 1) << 7;

    float mx = -INFINITY;
    for (int j = lane; j < len; j += 32) mx = fmaxf(mx, p[j]);
#pragma unroll
    for (int off = 16; off; off >>= 1)
        mx = fmaxf(mx, __shfl_xor_sync(~0u, mx, off));

    float sum = 0.f;
    for (int j = lane; j < len; j += 32) sum += __expf(p[j] - mx);
#pragma unroll
    for (int off = 16; off; off >>= 1)
        sum += __shfl_xor_sync(~0u, sum, off);
    const float inv = 1.f / sum;

    for (int j = lane; j < pe; j += 32) {
        float v = (j < len) ? __uint_as_float(f2tf(__expf(p[j] - mx) * inv)) : 0.f;
        p[j] = v;
    }
}

// ------------------- PV GEMM: lat = P @ KV -----------------------------------
// grid (n 4, qtile 16, bh 64); K = (qtile+1)*128.
__global__ __launch_bounds__(256) void pv_gemm(void)
{
    __shared__ unsigned sA[128 * GKS];
    __shared__ unsigned sB[128 * GKS];

    const int z = blockIdx.z;
    const int b = z >> 4, h = z & 15;
    const float* A = g_score + (size_t)z * S_ * S_;
    const float* B = g_k576 + (size_t)b * S_ * DK_;   // cols 0..511 = latent
    float* C = g_lat + ((size_t)h * MT + (size_t)b * S_) * KL_;

    const int tid = threadIdx.x;
    const int warp = tid >> 5, lane = tid & 31;
    const int gid = lane >> 2, tig = lane & 3;
    const int m0 = blockIdx.y * 128, n0 = blockIdx.x * 128;
    const int wm = (warp & 3) * 32;
    const int wn = (warp >> 2) * 64;
    const int K = (blockIdx.y + 1) * 128;

    float acc[2][8][4];
#pragma unroll
    for (int mt = 0; mt < 2; mt++)
#pragma unroll
        for (int nt = 0; nt < 8; nt++)
#pragma unroll
            for (int j = 0; j < 4; j++) acc[mt][nt][j] = 0.f;

    for (int k0 = 0; k0 < K; k0 += 32) {
#pragma unroll
        for (int i = 0; i < 4; i++) {
            const int lin = tid + i * 256;
            const int r = lin >> 3, c4 = (lin & 7) * 4;
            uint4 v = *(const uint4*)(A + (size_t)(m0 + r) * S_ + k0 + c4);
            *(uint4*)(sA + r * GKS + c4) = v;     // P already tf32
        }
#pragma unroll
        for (int i = 0; i < 16; i++) {
            const int lin = tid + i * 256;
            const int n = lin & 127, k = lin >> 7;
            // kv pre-rounded tf32: raw bits
            sB[n * GKS + k] = ((const unsigned*)B)[(size_t)(k0 + k) * DK_ + n0 + n];
        }
        __syncthreads();
        mma_block_32(sA, sB, acc, wm, wn, gid, tig);
        __syncthreads();
    }

#pragma unroll
    for (int mt = 0; mt < 2; mt++) {
        const int r0 = m0 + wm + mt * 16 + gid;
#pragma unroll
        for (int nt = 0; nt < 8; nt++) {
            const int col = n0 + wn + nt * 8 + tig * 2;
            *(float2*)(C + (size_t)r0 * KL_ + col) =
                make_float2(acc[mt][nt][0], acc[mt][nt][1]);
            *(float2*)(C + (size_t)(r0 + 8) * KL_ + col) =
                make_float2(acc[mt][nt][2], acc[mt][nt][3]);
        }
    }
}

// ------------------- rmsnorm (in place, strided), optional tf32 round --------
__global__ void rmsnorm_kernel(float* __restrict__ data,
                               const float* __restrict__ gamma,
                               int width, int stride, int tf32out)
{
    float* p = data + (size_t)blockIdx.x * stride;
    const int tid = threadIdx.x;
    float ss = 0.f;
    for (int i = tid * 4; i < width; i += 512) {
        float4 v = *(const float4*)(p + i);
        ss += v.x * v.x + v.y * v.y + v.z * v.z + v.w * v.w;
    }
#pragma unroll
    for (int off = 16; off; off >>= 1) ss += __shfl_xor_sync(~0u, ss, off);
    __shared__ float ws[4];
    if ((tid & 31) == 0) ws[tid >> 5] = ss;
    __syncthreads();
    const float inv = rsqrtf((ws[0] + ws[1] + ws[2] + ws[3]) / (float)width + 1e-6f);
    for (int i = tid * 4; i < width; i += 512) {
        float4 v = *(const float4*)(p + i);
        float4 g = *(const float4*)(gamma + i);
        v.x *= inv * g.x; v.y *= inv * g.y; v.z *= inv * g.z; v.w *= inv * g.w;
        if (tf32out) {
            v.x = __uint_as_float(f2tf(v.x)); v.y = __uint_as_float(f2tf(v.y));
            v.z = __uint_as_float(f2tf(v.z)); v.w = __uint_as_float(f2tf(v.w));
        }
        *(float4*)(p + i) = v;
    }
}

// ------------------- RoPE: read gemm out, write into 576 buffers --------------
__global__ void rope_q_kernel(const float* __restrict__ qr)   // [MT][H*64]
{
    const int idx = blockIdx.x * 256 + threadIdx.x;
    const int i = idx & 31, rest = idx >> 5;
    const int h = rest & (H_ - 1), m = rest >> 4;
    const float* s = qr + (size_t)m * (H_ * RD_) + h * RD_;
    const float x1 = s[i], x2 = s[i + 32];
    const float pos = (float)(m & (S_ - 1));
    const float inv_freq = exp2f(-(float)i * (13.287712379549449f / 32.f));
    float sn, cs;
    sincosf(pos * inv_freq, &sn, &cs);
    float* d = g_q576 + ((size_t)h * MT + m) * DK_ + KL_;
    d[i]      = __uint_as_float(f2tf((x1 * cs - x2 * sn) * SM_SCALE));
    d[i + 32] = __uint_as_float(f2tf((x1 * sn + x2 * cs) * SM_SCALE));
}

__global__ void rope_k_kernel(const float* __restrict__ kr)   // [MT][64]
{
    const int idx = blockIdx.x * 256 + threadIdx.x;
    const int i = idx & 31, m = idx >> 5;
    const float* s = kr + (size_t)m * RD_;
    const float x1 = s[i], x2 = s[i + 32];
    const float pos = (float)(m & (S_ - 1));
    const float inv_freq = exp2f(-(float)i * (13.287712379549449f / 32.f));
    float sn, cs;
    sincosf(pos * inv_freq, &sn, &cs);
    float* d = g_k576 + (size_t)m * DK_ + KL_;
    d[i]      = __uint_as_float(f2tf(x1 * cs - x2 * sn));
    d[i + 32] = __uint_as_float(f2tf(x1 * sn + x2 * cs));
}

// ------------------- launch ---------------------------------------------------
extern "C" void kernel_launch(void* const* d_in, const int* in_sizes, int n_in,
                              void* d_out, int out_size)
{
    const float* x      = (const float*)d_in[0];
    const float* w_qd   = (const float*)d_in[3];
    const float* b_qd   = (const float*)d_in[4];
    const float* gam_q  = (const float*)d_in[5];
    const float* w_qn   = (const float*)d_in[6];
    const float* b_qn   = (const float*)d_in[7];
    const float* w_qr   = (const float*)d_in[8];
    const float* b_qr   = (const float*)d_in[9];
    const float* w_kvd  = (const float*)d_in[10];
    const float* b_kvd  = (const float*)d_in[11];
    const float* gam_kv = (const float*)d_in[12];
    const float* w_ku   = (const float*)d_in[13];
    const float* w_vu   = (const float*)d_in[15];
    const float* w_kr   = (const float*)d_in[17];
    const float* b_kr   = (const float*)d_in[18];
    const float* gates  = (const float*)d_in[19];
    const float* w_o    = (const float*)d_in[20];
    const float* b_o    = (const float*)d_in[21];
    float* out = (float*)d_out;

    float *qc, *qnope, *qrope, *krope, *q576, *k576, *lat, *outhd;
    cudaGetSymbolAddress((void**)&qc,    g_qc);
    cudaGetSymbolAddress((void**)&qnope, g_qnope);
    cudaGetSymbolAddress((void**)&qrope, g_qrope);
    cudaGetSymbolAddress((void**)&krope, g_krope);
    cudaGetSymbolAddress((void**)&q576,  g_q576);
    cudaGetSymbolAddress((void**)&k576,  g_k576);
    cudaGetSymbolAddress((void**)&lat,   g_lat);
    cudaGetSymbolAddress((void**)&outhd, g_outhd);

    dim3 blk(256);
    // qc = rmsnorm(x @ w_qd^T + b_qd)
    gemm_tf32<true><<<dim3(QL_ / 128, MT / 128, 1), blk>>>(
        x, D_, 0, w_qd, D_, 0, qc, QL_, 0, QL_, D_, b_qd, nullptr, 1.f, 0);
    rmsnorm_kernel<<<MT, 128>>>(qc, gam_q, QL_, QL_, 0);
    // q_nope
    gemm_tf32<true><<<dim3(D_ / 128, MT / 128, 1), blk>>>(
        qc, QL_, 0, w_qn, QL_, 0, qnope, D_, 0, D_, QL_, b_qn, nullptr, 1.f, 0);
    // q_rope -> rope -> q576 tail cols (scaled, tf32)
    gemm_tf32<true><<<dim3((H_ * RD_) / 128, MT / 128, 1), blk>>>(
        qc, QL_, 0, w_qr, QL_, 0, qrope, H_ * RD_, 0, H_ * RD_, QL_, b_qr, nullptr,
        1.f, 0);
    rope_q_kernel<<<MT * H_ * 32 / 256, 256>>>(qrope);
    // kv -> k576 cols 0..511 (rmsnorm strided, tf32)
    gemm_tf32<true><<<dim3(KL_ / 128, MT / 128, 1), blk>>>(
        x, D_, 0, w_kvd, D_, 0, k576, DK_, 0, KL_, D_, b_kvd, nullptr, 1.f, 0);
    rmsnorm_kernel<<<MT, 128>>>(k576, gam_kv, KL_, DK_, 1);
    // k_rope -> rope -> k576 tail cols (tf32)
    gemm_tf32<true><<<dim3(1, MT / 128, 1), blk>>>(
        x, D_, 0, w_kr, D_, 0, krope, RD_, 0, RD_, D_, b_kr, nullptr, 1.f, 0);
    rope_k_kernel<<<MT * 32 / 256, 256>>>(krope);
    // q_abs -> q576 cols 0..511 (scaled, tf32)
    gemm_tf32<false><<<dim3(KL_ / 128, MT / 128, H_), blk>>>(
        qnope, D_, HD_, w_ku, KL_, (long long)HD_ * KL_,
        q576, DK_, (long long)MT * DK_, KL_, HD_, nullptr, nullptr,
        SM_SCALE, 1);
    // attention: score -> softmax -> PV
    score_gemm<<<dim3(S_ / 128, S_ / 128, B_ * H_), blk>>>();
    softmax_rows<<<(B_ * H_ * S_) / 8, 256>>>();
    pv_gemm<<<dim3(KL_ / 128, S_ / 128, B_ * H_), blk>>>();
    // out_h = (lat_h @ w_vu[h]^T) * sigmoid(gate[h])
    gemm_tf32<true><<<dim3(1, MT / 128, H_), blk>>>(
        lat, KL_, (long long)MT * KL_, w_vu, KL_, (long long)HD_ * KL_,
        outhd, D_, HD_, HD_, KL_, nullptr, gates, 1.f, 0);
    // final projection
    gemm_tf32<true><<<dim3(D_ / 128, MT / 128, 1), blk>>>(
        outhd, D_, 0, w_o, D_, 0, out, D_, 0, D_, D_, b_o, nullptr, 1.f, 0);
}

// round 12
// speedup vs baseline: 1.5738x; 1.5738x over previous
#include <cuda_runtime.h>
#include <cuda_bf16.h>
#include <math.h>

#define B_  4
#define S_  2048
#define D_  2048
#define H_  16
#define HD_ 128
#define RD_ 64
#define QL_ 512
#define KL_ 512
#define MT  (B_*S_)
#define SM_SCALE 0.07216878364870323f  // 1/sqrt(192)

// ------------------- scratch (device globals; no runtime allocs) ------------
__device__ float g_qc   [(size_t)MT * QL_];
__device__ float g_qnope[(size_t)MT * D_];          // scaled tf32
__device__ float g_qrope[(size_t)MT * (H_ * RD_)];  // scaled tf32
__device__ float g_kvl  [(size_t)MT * KL_];         // tf32
__device__ float g_krope[(size_t)MT * RD_];         // tf32
__device__ float g_kabs [(size_t)H_ * MT * HD_];    // tf32
__device__ float g_lat  [(size_t)H_ * MT * KL_];
__device__ float g_outhd[(size_t)MT * D_];

// ------------------- tf32 mma helpers ----------------------------------------
__device__ __forceinline__ unsigned f2tf(float f)
{
    unsigned u; asm("cvt.rna.tf32.f32 %0, %1;" : "=r"(u) : "f"(f)); return u;
}
__device__ __forceinline__ void mma_tf32(float c[4],
    unsigned a0, unsigned a1, unsigned a2, unsigned a3,
    unsigned b0, unsigned b1)
{
    asm volatile("mma.sync.aligned.m16n8k8.row.col.f32.tf32.tf32.f32 "
                 "{%0,%1,%2,%3},{%4,%5,%6,%7},{%8,%9},{%0,%1,%2,%3};"
                 : "+f"(c[0]), "+f"(c[1]), "+f"(c[2]), "+f"(c[3])
                 : "r"(a0), "r"(a1), "r"(a2), "r"(a3), "r"(b0), "r"(b1));
}
__device__ __forceinline__ void cp16(void* smem, const void* gmem)
{
    unsigned s = (unsigned)__cvta_generic_to_shared(smem);
    asm volatile("cp.async.cg.shared.global [%0], [%1], 16;\n" :: "r"(s), "l"(gmem));
}
#define CP_COMMIT() asm volatile("cp.async.commit_group;\n" ::: "memory")
#define CP_WAIT1()  asm volatile("cp.async.wait_group 1;\n" ::: "memory")
#define CP_WAIT0()  asm volatile("cp.async.wait_group 0;\n" ::: "memory")

// ------------------- tf32 tensor-core GEMM (projections) ----------------------
#define GKS 36
template<bool TRANSB>
__global__ __launch_bounds__(256) void gemm_tf32(
    const float* __restrict__ A, int lda, long long sAz,
    const float* __restrict__ B, int ldb, long long sBz,
    float* __restrict__ C, int ldc, long long sCz,
    int N, int K,
    const float* __restrict__ bias,
    const float* __restrict__ gates,
    float uscale, int tf32out)
{
    __shared__ unsigned sA[128 * GKS];
    __shared__ unsigned sB[128 * GKS];

    const int z = blockIdx.z;
    A += (long long)z * sAz;  B += (long long)z * sBz;  C += (long long)z * sCz;

    const int tid = threadIdx.x;
    const int warp = tid >> 5, lane = tid & 31;
    const int gid = lane >> 2, tig = lane & 3;
    const int m0 = blockIdx.y * 128, n0 = blockIdx.x * 128;
    const int wm = (warp & 3) * 32;
    const int wn = (warp >> 2) * 64;

    float acc[2][8][4];
#pragma unroll
    for (int mt = 0; mt < 2; mt++)
#pragma unroll
        for (int nt = 0; nt < 8; nt++)
#pragma unroll
            for (int j = 0; j < 4; j++) acc[mt][nt][j] = 0.f;

    for (int k0 = 0; k0 < K; k0 += 32) {
#pragma unroll
        for (int i = 0; i < 4; i++) {
            const int lin = tid + i * 256;
            const int r = lin >> 3, c4 = (lin & 7) * 4;
            float4 v = *(const float4*)(A + (long long)(m0 + r) * lda + k0 + c4);
            unsigned* d = sA + r * GKS + c4;
            d[0] = f2tf(v.x); d[1] = f2tf(v.y); d[2] = f2tf(v.z); d[3] = f2tf(v.w);
        }
        if (TRANSB) {
#pragma unroll
            for (int i = 0; i < 4; i++) {
                const int lin = tid + i * 256;
                const int r = lin >> 3, c4 = (lin & 7) * 4;
                float4 v = make_float4(0.f, 0.f, 0.f, 0.f);
                if (n0 + r < N)
                    v = *(const float4*)(B + (long long)(n0 + r) * ldb + k0 + c4);
                unsigned* d = sB + r * GKS + c4;
                d[0] = f2tf(v.x); d[1] = f2tf(v.y); d[2] = f2tf(v.z); d[3] = f2tf(v.w);
            }
        } else {
#pragma unroll
            for (int i = 0; i < 16; i++) {
                const int lin = tid + i * 256;
                const int n = lin & 127, k = lin >> 7;
                float v = (n0 + n < N) ? B[(long long)(k0 + k) * ldb + n0 + n] : 0.f;
                sB[n * GKS + k] = f2tf(v);
            }
        }
        __syncthreads();
#pragma unroll
        for (int kk = 0; kk < 4; kk++) {
            const int k8 = kk * 8;
            unsigned a[2][4], b[8][2];
#pragma unroll
            for (int mt = 0; mt < 2; mt++) {
                const unsigned* p = sA + (wm + mt * 16 + gid) * GKS + k8 + tig;
                a[mt][0] = p[0];
                a[mt][1] = p[8 * GKS];
                a[mt][2] = p[4];
                a[mt][3] = p[8 * GKS + 4];
            }
#pragma unroll
            for (int nt = 0; nt < 8; nt++) {
                const unsigned* p = sB + (wn + nt * 8 + gid) * GKS + k8 + tig;
                b[nt][0] = p[0];
                b[nt][1] = p[4];
            }
#pragma unroll
            for (int mt = 0; mt < 2; mt++)
#pragma unroll
                for (int nt = 0; nt < 8; nt++)
                    mma_tf32(acc[mt][nt], a[mt][0], a[mt][1], a[mt][2], a[mt][3],
                             b[nt][0], b[nt][1]);
        }
        __syncthreads();
    }

    float scale = uscale;
    if (gates) scale *= 1.f / (1.f + expf(-gates[z]));
#pragma unroll
    for (int mt = 0; mt < 2; mt++) {
        const int r0 = m0 + wm + mt * 16 + gid;
#pragma unroll
        for (int nt = 0; nt < 8; nt++) {
            const int col = n0 + wn + nt * 8 + tig * 2;
            if (col < N) {
                float bx = 0.f, by = 0.f;
                if (bias) { bx = bias[col]; by = bias[col + 1]; }
                float v00 = (acc[mt][nt][0] + bx) * scale;
                float v01 = (acc[mt][nt][1] + by) * scale;
                float v10 = (acc[mt][nt][2] + bx) * scale;
                float v11 = (acc[mt][nt][3] + by) * scale;
                if (tf32out) {
                    v00 = __uint_as_float(f2tf(v00));
                    v01 = __uint_as_float(f2tf(v01));
                    v10 = __uint_as_float(f2tf(v10));
                    v11 = __uint_as_float(f2tf(v11));
                }
                *(float2*)(C + (long long)r0 * ldc + col)       = make_float2(v00, v01);
                *(float2*)(C + (long long)(r0 + 8) * ldc + col) = make_float2(v10, v11);
            }
        }
    }
}

// ------------------- rmsnorm (in place), optional tf32 round ------------------
__global__ void rmsnorm_kernel(float* __restrict__ data,
                               const float* __restrict__ gamma,
                               int width, int tf32out)
{
    float* p = data + (size_t)blockIdx.x * width;
    const int tid = threadIdx.x;
    float ss = 0.f;
    for (int i = tid * 4; i < width; i += 512) {
        float4 v = *(const float4*)(p + i);
        ss += v.x * v.x + v.y * v.y + v.z * v.z + v.w * v.w;
    }
#pragma unroll
    for (int off = 16; off; off >>= 1) ss += __shfl_xor_sync(~0u, ss, off);
    __shared__ float ws[4];
    if ((tid & 31) == 0) ws[tid >> 5] = ss;
    __syncthreads();
    const float inv = rsqrtf((ws[0] + ws[1] + ws[2] + ws[3]) / (float)width + 1e-6f);
    for (int i = tid * 4; i < width; i += 512) {
        float4 v = *(const float4*)(p + i);
        float4 g = *(const float4*)(gamma + i);
        v.x *= inv * g.x; v.y *= inv * g.y; v.z *= inv * g.z; v.w *= inv * g.w;
        if (tf32out) {
            v.x = __uint_as_float(f2tf(v.x)); v.y = __uint_as_float(f2tf(v.y));
            v.z = __uint_as_float(f2tf(v.z)); v.w = __uint_as_float(f2tf(v.w));
        }
        *(float4*)(p + i) = v;
    }
}

// ------------------- RoPE (in place), tf32-rounded ----------------------------
__device__ __forceinline__ void rope_pair(float* p, int i, int m, float scale)
{
    const float x1 = p[i], x2 = p[i + 32];
    const float pos = (float)(m & (S_ - 1));
    const float inv_freq = exp2f(-(float)i * (13.287712379549449f / 32.f));
    float sn, cs;
    sincosf(pos * inv_freq, &sn, &cs);
    p[i]      = __uint_as_float(f2tf((x1 * cs - x2 * sn) * scale));
    p[i + 32] = __uint_as_float(f2tf((x1 * sn + x2 * cs) * scale));
}

__global__ void rope_q_kernel(float* __restrict__ q)
{
    const int idx = blockIdx.x * 256 + threadIdx.x;
    const int i = idx & 31, rest = idx >> 5;
    const int h = rest & (H_ - 1), m = rest >> 4;
    rope_pair(q + (size_t)m * (H_ * RD_) + h * RD_, i, m, SM_SCALE);
}

__global__ void rope_k_kernel(float* __restrict__ k)
{
    const int idx = blockIdx.x * 256 + threadIdx.x;
    const int i = idx & 31, m = idx >> 5;
    rope_pair(k + (size_t)m * RD_, i, m, 1.f);
}

// ------------------- fused causal flash attention (k192 absorbed-K) -----------
// grid (S/32, H, B), 512 threads (16 warps). BM=32, BN=64, score k=192.
// smem: uQ[32][196], uK[64][196], uV[64][516], sP[32][68]. cp.async pipelined.
#define QKS 196
#define VST 516
#define PSTR 68
__global__ __launch_bounds__(512, 1) void mla_attn_kernel(
    const float* __restrict__ qnope,  // [MT][H*128] tf32*scale
    const float* __restrict__ qrope,  // [MT][H*64]  tf32*scale
    const float* __restrict__ kabs,   // [H][MT][128] tf32
    const float* __restrict__ krope,  // [MT][64]    tf32
    const float* __restrict__ kvl,    // [MT][512]   tf32
    float* __restrict__ lat)          // [H][MT][512]
{
    extern __shared__ float smf[];
    unsigned* uQ  = (unsigned*)smf;            // 32*196
    unsigned* uK  = uQ + 32 * QKS;             // 64*196
    unsigned* uV  = uK + 64 * QKS;             // 64*516
    float* sP     = (float*)(uV + 64 * VST);   // 32*68
    float* sAlpha = sP + 32 * PSTR;
    float* sL     = sAlpha + 32;
    unsigned* uP  = (unsigned*)sP;

    const int qt = blockIdx.x, h = blockIdx.y, b = blockIdx.z;
    const int tid = threadIdx.x;
    const int warp = tid >> 5, lane = tid & 31;
    const int gid = lane >> 2, tig = lane & 3;
    const long long mbase = (long long)b * S_;
    const int q0 = qt * 32;

    // ---- Q tile (plain loads): cols 0-127 qnope_h, 128-191 qrope_h
    {
        const unsigned* qn = (const unsigned*)qnope + (mbase + q0) * D_ + h * HD_;
#pragma unroll
        for (int i = 0; i < 2; i++) {
            const int idx = tid + i * 512;             // 1024: 32 rows x 32 u4
            const int r = idx >> 5, cu = idx & 31;
            uint4 v = *(const uint4*)(qn + (long long)r * D_ + cu * 4);
            *(uint4*)(uQ + r * QKS + cu * 4) = v;
        }
        const unsigned* qr = (const unsigned*)qrope + (mbase + q0) * (H_ * RD_) + h * RD_;
        {
            const int r = tid >> 4, cu = tid & 15;     // 512: 32 rows x 16 u4
            uint4 v = *(const uint4*)(qr + (long long)r * (H_ * RD_) + cu * 4);
            *(uint4*)(uQ + r * QKS + 128 + cu * 4) = v;
        }
    }

    const unsigned* kab = (const unsigned*)kabs + ((long long)h * MT + mbase) * HD_;
    const unsigned* krp = (const unsigned*)krope + mbase * RD_;
    const unsigned* kvp = (const unsigned*)kvl + mbase * KL_;

    // score roles: warp = m16 x n8 x k192
    const int mh = warp >> 3;            // 0..1
    const int nh = warp & 7;             // 0..7
    const int m0w = mh * 16, n0w = nh * 8;

    // softmax ownership: 16 thr/row x 4 cols
    const int srow = tid >> 4;
    const int scb  = (tid & 15) * 4;
    float m_run = -INFINITY, l_run = 0.f;

    // PV roles: warp = m16 x n64
    const int mg  = warp & 1;
    const int pc0 = (warp >> 1) * 64;
    float acc[8][4];
#pragma unroll
    for (int nt = 0; nt < 8; nt++)
#pragma unroll
        for (int j = 0; j < 4; j++) acc[nt][j] = 0.f;

    const int ntiles = (q0 + 31) / 64 + 1;

    // prologue: prefetch K_0
    {
        const int t0 = 0;
#pragma unroll
        for (int i = 0; i < 4; i++) {
            const int idx = tid + i * 512;
            const int r = idx >> 5, cu = idx & 31;
            cp16(uK + r * QKS + cu * 4, kab + (long long)(t0 + r) * HD_ + cu * 4);
        }
#pragma unroll
        for (int i = 0; i < 2; i++) {
            const int idx = tid + i * 512;
            const int r = idx >> 4, cu = idx & 15;
            cp16(uK + r * QKS + 128 + cu * 4, krp + (long long)(t0 + r) * RD_ + cu * 4);
        }
        CP_COMMIT();
    }

    for (int tt = 0; tt < ntiles; tt++) {
        const int t0 = tt * 64;
        __syncthreads();                 // prev PV done with uV / sP
        // issue V_t
#pragma unroll
        for (int i = 0; i < 16; i++) {
            const int idx = tid + i * 512;
            const int r = idx >> 7, cu = idx & 127;
            cp16(uV + r * VST + cu * 4, kvp + (long long)(t0 + r) * KL_ + cu * 4);
        }
        CP_COMMIT();
        CP_WAIT1();                      // K_t complete (V_t pending)
        __syncthreads();

        // ---- score: m16 x n8 x k192 per warp
        float c[4] = {0.f, 0.f, 0.f, 0.f};
        {
            const unsigned* qp0 = uQ + (m0w + gid) * QKS + tig;
            const unsigned* qp1 = uQ + (m0w + gid + 8) * QKS + tig;
            const unsigned* kb  = uK + (n0w + gid) * QKS + tig;
#pragma unroll
            for (int kc = 0; kc < 24; kc++) {
                const int k = kc * 8;
                mma_tf32(c, qp0[k], qp1[k], qp0[k + 4], qp1[k + 4],
                         kb[k], kb[k + 4]);
            }
        }
        {
            float* p0 = sP + (m0w + gid) * PSTR + n0w + tig * 2;
            float* p1 = sP + (m0w + gid + 8) * PSTR + n0w + tig * 2;
            *(float2*)p0 = make_float2(c[0], c[1]);
            *(float2*)p1 = make_float2(c[2], c[3]);
        }
        __syncthreads();                 // scores visible; uK free

        // prefetch K_{t+1} (clamped; redundant on last tile)
        {
            const int tn = (tt + 1 < ntiles) ? (tt + 1) * 64 : t0;
#pragma unroll
            for (int i = 0; i < 4; i++) {
                const int idx = tid + i * 512;
                const int r = idx >> 5, cu = idx & 31;
                cp16(uK + r * QKS + cu * 4, kab + (long long)(tn + r) * HD_ + cu * 4);
            }
#pragma unroll
            for (int i = 0; i < 2; i++) {
                const int idx = tid + i * 512;
                const int r = idx >> 4, cu = idx & 15;
                cp16(uK + r * QKS + 128 + cu * 4, krp + (long long)(tn + r) * RD_ + cu * 4);
            }
            CP_COMMIT();
        }

        // ---- online softmax (scale pre-folded into Q)
        {
            const int rglob = q0 + srow;
            float s[4];
            float4 v0 = *(const float4*)&sP[srow * PSTR + scb];
            s[0] = v0.x; s[1] = v0.y; s[2] = v0.z; s[3] = v0.w;
            float mx = -INFINITY;
#pragma unroll
            for (int j = 0; j < 4; j++) {
                if (t0 + scb + j > rglob) s[j] = -INFINITY;
                mx = fmaxf(mx, s[j]);
            }
#pragma unroll
            for (int off = 1; off < 16; off <<= 1)
                mx = fmaxf(mx, __shfl_xor_sync(~0u, mx, off, 16));
            const float mnew = fmaxf(m_run, mx);
            const float alpha = __expf(m_run - mnew);
            float lsum = 0.f;
#pragma unroll
            for (int j = 0; j < 4; j++) { s[j] = __expf(s[j] - mnew); lsum += s[j]; }
#pragma unroll
            for (int off = 1; off < 16; off <<= 1)
                lsum += __shfl_xor_sync(~0u, lsum, off, 16);
            l_run = l_run * alpha + lsum;
            m_run = mnew;
            unsigned* d = uP + srow * PSTR + scb;
#pragma unroll
            for (int j = 0; j < 4; j++) d[j] = f2tf(s[j]);
            if ((tid & 15) == 0) sAlpha[srow] = alpha;
        }
        CP_WAIT1();                      // V_t complete (K_{t+1} pending)
        __syncthreads();                 // softmax + V visible

        // ---- PV: warp = m16 x n64, acc = acc*alpha + P @ V
        {
            const float a0r = sAlpha[mg * 16 + gid];
            const float a1r = sAlpha[mg * 16 + gid + 8];
#pragma unroll
            for (int nt = 0; nt < 8; nt++) {
                acc[nt][0] *= a0r; acc[nt][1] *= a0r;
                acc[nt][2] *= a1r; acc[nt][3] *= a1r;
            }
#pragma unroll
            for (int kc = 0; kc < 8; kc++) {
                const int kk = kc * 8;
                const unsigned* pp = uP + (mg * 16 + gid) * PSTR + kk + tig;
                unsigned pa0 = pp[0];
                unsigned pa1 = pp[8 * PSTR];
                unsigned pa2 = pp[4];
                unsigned pa3 = pp[8 * PSTR + 4];
                const unsigned* v0 = uV + (kk + tig) * VST + pc0 + gid;
                const unsigned* v1 = uV + (kk + tig + 4) * VST + pc0 + gid;
#pragma unroll
                for (int nt = 0; nt < 8; nt++)
                    mma_tf32(acc[nt], pa0, pa1, pa2, pa3, v0[nt * 8], v1[nt * 8]);
            }
        }
    }
    CP_WAIT0();

    // ---- epilogue
    if ((tid & 15) == 0) sL[srow] = l_run;
    __syncthreads();
    const float invL = 1.f / sL[mg * 16 + gid];
    const float invH = 1.f / sL[mg * 16 + gid + 8];
    const int rL = mg * 16 + gid, rH = rL + 8;
    float* outp = lat + ((long long)h * MT + mbase + q0) * KL_;
#pragma unroll
    for (int nt = 0; nt < 8; nt++) {
        const int col = pc0 + nt * 8 + tig * 2;
        *(float2*)(outp + (long long)rL * KL_ + col) =
            make_float2(acc[nt][0] * invL, acc[nt][1] * invL);
        *(float2*)(outp + (long long)rH * KL_ + col) =
            make_float2(acc[nt][2] * invH, acc[nt][3] * invH);
    }
}

// ------------------- launch ---------------------------------------------------
extern "C" void kernel_launch(void* const* d_in, const int* in_sizes, int n_in,
                              void* d_out, int out_size)
{
    const float* x      = (const float*)d_in[0];
    const float* w_qd   = (const float*)d_in[3];
    const float* b_qd   = (const float*)d_in[4];
    const float* gam_q  = (const float*)d_in[5];
    const float* w_qn   = (const float*)d_in[6];
    const float* b_qn   = (const float*)d_in[7];
    const float* w_qr   = (const float*)d_in[8];
    const float* b_qr   = (const float*)d_in[9];
    const float* w_kvd  = (const float*)d_in[10];
    const float* b_kvd  = (const float*)d_in[11];
    const float* gam_kv = (const float*)d_in[12];
    const float* w_ku   = (const float*)d_in[13];
    const float* w_vu   = (const float*)d_in[15];
    const float* w_kr   = (const float*)d_in[17];
    const float* b_kr   = (const float*)d_in[18];
    const float* gates  = (const float*)d_in[19];
    const float* w_o    = (const float*)d_in[20];
    const float* b_o    = (const float*)d_in[21];
    float* out = (float*)d_out;

    float *qc, *qnope, *qrope, *kvl, *krope, *kabs, *lat, *outhd;
    cudaGetSymbolAddress((void**)&qc,    g_qc);
    cudaGetSymbolAddress((void**)&qnope, g_qnope);
    cudaGetSymbolAddress((void**)&qrope, g_qrope);
    cudaGetSymbolAddress((void**)&kvl,   g_kvl);
    cudaGetSymbolAddress((void**)&krope, g_krope);
    cudaGetSymbolAddress((void**)&kabs,  g_kabs);
    cudaGetSymbolAddress((void**)&lat,   g_lat);
    cudaGetSymbolAddress((void**)&outhd, g_outhd);

    const int smem_attn = (32 * QKS + 64 * QKS + 64 * VST + 32 * PSTR + 64)
                          * sizeof(float);
    cudaFuncSetAttribute(mla_attn_kernel,
                         cudaFuncAttributeMaxDynamicSharedMemorySize, smem_attn);

    dim3 blk(256);
    // qc = rmsnorm(x @ w_qd^T + b_qd)
    gemm_tf32<true><<<dim3(QL_ / 128, MT / 128, 1), blk>>>(
        x, D_, 0, w_qd, D_, 0, qc, QL_, 0, QL_, D_, b_qd, nullptr, 1.f, 0);
    rmsnorm_kernel<<<MT, 128>>>(qc, gam_q, QL_, 0);
    // q_nope, scaled + tf32
    gemm_tf32<true><<<dim3(D_ / 128, MT / 128, 1), blk>>>(
        qc, QL_, 0, w_qn, QL_, 0, qnope, D_, 0, D_, QL_, b_qn, nullptr,
        SM_SCALE, 1);
    // q_rope -> rope (scaled, tf32, in place)
    gemm_tf32<true><<<dim3((H_ * RD_) / 128, MT / 128, 1), blk>>>(
        qc, QL_, 0, w_qr, QL_, 0, qrope, H_ * RD_, 0, H_ * RD_, QL_, b_qr, nullptr,
        1.f, 0);
    rope_q_kernel<<<MT * H_ * 32 / 256, 256>>>(qrope);
    // kv latent = rmsnorm(x @ w_kvd^T + b_kvd), tf32
    gemm_tf32<true><<<dim3(KL_ / 128, MT / 128, 1), blk>>>(
        x, D_, 0, w_kvd, D_, 0, kvl, KL_, 0, KL_, D_, b_kvd, nullptr, 1.f, 0);
    rmsnorm_kernel<<<MT, 128>>>(kvl, gam_kv, KL_, 1);
    // k_rope -> rope (tf32, in place)
    gemm_tf32<true><<<dim3(1, MT / 128, 1), blk>>>(
        x, D_, 0, w_kr, D_, 0, krope, RD_, 0, RD_, D_, b_kr, nullptr, 1.f, 0);
    rope_k_kernel<<<MT * 32 / 256, 256>>>(krope);
    // k_abs[h] = kvl @ w_uk[h]^T  (tf32)
    gemm_tf32<true><<<dim3(1, MT / 128, H_), blk>>>(
        kvl, KL_, 0, w_ku, KL_, (long long)HD_ * KL_,
        kabs, HD_, (long long)MT * HD_, HD_, KL_, nullptr, nullptr, 1.f, 1);
    // fused attention
    mla_attn_kernel<<<dim3(S_ / 32, H_, B_), dim3(512), smem_attn>>>(
        qnope, qrope, kabs, krope, kvl, lat);
    // out_h = (lat_h @ w_vu[h]^T) * sigmoid(gate[h])
    gemm_tf32<true><<<dim3(1, MT / 128, H_), blk>>>(
        lat, KL_, (long long)MT * KL_, w_vu, KL_, (long long)HD_ * KL_,
        outhd, D_, HD_, HD_, KL_, nullptr, gates, 1.f, 0);
    // final projection
    gemm_tf32<true><<<dim3(D_ / 128, MT / 128, 1), blk>>>(
        outhd, D_, 0, w_o, D_, 0, out, D_, 0, D_, D_, b_o, nullptr, 1.f, 0);
}

// round 13
// speedup vs baseline: 2.0070x; 1.2752x over previous
#include <cuda_runtime.h>
#include <cuda_bf16.h>
#include <math.h>

#define B_  4
#define S_  2048
#define D_  2048
#define H_  16
#define HD_ 128
#define RD_ 64
#define QL_ 512
#define KL_ 512
#define MT  (B_*S_)
#define SM_SCALE 0.07216878364870323f  // 1/sqrt(192)

// ------------------- scratch (device globals; no runtime allocs) ------------
__device__ float g_qc   [(size_t)MT * QL_];
__device__ float g_qnope[(size_t)MT * D_];          // scaled tf32
__device__ float g_qrope[(size_t)MT * (H_ * RD_)];  // scaled tf32
__device__ float g_kvl  [(size_t)MT * KL_];         // tf32
__device__ float g_krope[(size_t)MT * RD_];         // tf32
__device__ float g_kabs [(size_t)H_ * MT * HD_];    // tf32
__device__ float g_lat  [(size_t)H_ * MT * KL_];
__device__ float g_outhd[(size_t)MT * D_];

// ------------------- tf32 mma helpers ----------------------------------------
__device__ __forceinline__ unsigned f2tf(float f)
{
    unsigned u; asm("cvt.rna.tf32.f32 %0, %1;" : "=r"(u) : "f"(f)); return u;
}
__device__ __forceinline__ void mma_tf32(float c[4],
    unsigned a0, unsigned a1, unsigned a2, unsigned a3,
    unsigned b0, unsigned b1)
{
    asm volatile("mma.sync.aligned.m16n8k8.row.col.f32.tf32.tf32.f32 "
                 "{%0,%1,%2,%3},{%4,%5,%6,%7},{%8,%9},{%0,%1,%2,%3};"
                 : "+f"(c[0]), "+f"(c[1]), "+f"(c[2]), "+f"(c[3])
                 : "r"(a0), "r"(a1), "r"(a2), "r"(a3), "r"(b0), "r"(b1));
}
__device__ __forceinline__ void cp16(void* smem, const void* gmem)
{
    unsigned s = (unsigned)__cvta_generic_to_shared(smem);
    asm volatile("cp.async.cg.shared.global [%0], [%1], 16;\n" :: "r"(s), "l"(gmem));
}
#define CP_COMMIT() asm volatile("cp.async.commit_group;\n" ::: "memory")
#define CP_WAIT1()  asm volatile("cp.async.wait_group 1;\n" ::: "memory")
#define CP_WAIT0()  asm volatile("cp.async.wait_group 0;\n" ::: "memory")

// ------------------- tf32 tensor-core GEMM (projections) ----------------------
#define GKS 36
template<bool TRANSB>
__global__ __launch_bounds__(256) void gemm_tf32(
    const float* __restrict__ A, int lda, long long sAz,
    const float* __restrict__ B, int ldb, long long sBz,
    float* __restrict__ C, int ldc, long long sCz,
    int N, int K,
    const float* __restrict__ bias,
    const float* __restrict__ gates,
    float uscale, int tf32out)
{
    __shared__ unsigned sA[128 * GKS];
    __shared__ unsigned sB[128 * GKS];

    const int z = blockIdx.z;
    A += (long long)z * sAz;  B += (long long)z * sBz;  C += (long long)z * sCz;

    const int tid = threadIdx.x;
    const int warp = tid >> 5, lane = tid & 31;
    const int gid = lane >> 2, tig = lane & 3;
    const int m0 = blockIdx.y * 128, n0 = blockIdx.x * 128;
    const int wm = (warp & 3) * 32;
    const int wn = (warp >> 2) * 64;

    float acc[2][8][4];
#pragma unroll
    for (int mt = 0; mt < 2; mt++)
#pragma unroll
        for (int nt = 0; nt < 8; nt++)
#pragma unroll
            for (int j = 0; j < 4; j++) acc[mt][nt][j] = 0.f;

    for (int k0 = 0; k0 < K; k0 += 32) {
#pragma unroll
        for (int i = 0; i < 4; i++) {
            const int lin = tid + i * 256;
            const int r = lin >> 3, c4 = (lin & 7) * 4;
            float4 v = *(const float4*)(A + (long long)(m0 + r) * lda + k0 + c4);
            unsigned* d = sA + r * GKS + c4;
            d[0] = f2tf(v.x); d[1] = f2tf(v.y); d[2] = f2tf(v.z); d[3] = f2tf(v.w);
        }
        if (TRANSB) {
#pragma unroll
            for (int i = 0; i < 4; i++) {
                const int lin = tid + i * 256;
                const int r = lin >> 3, c4 = (lin & 7) * 4;
                float4 v = make_float4(0.f, 0.f, 0.f, 0.f);
                if (n0 + r < N)
                    v = *(const float4*)(B + (long long)(n0 + r) * ldb + k0 + c4);
                unsigned* d = sB + r * GKS + c4;
                d[0] = f2tf(v.x); d[1] = f2tf(v.y); d[2] = f2tf(v.z); d[3] = f2tf(v.w);
            }
        } else {
#pragma unroll
            for (int i = 0; i < 16; i++) {
                const int lin = tid + i * 256;
                const int n = lin & 127, k = lin >> 7;
                float v = (n0 + n < N) ? B[(long long)(k0 + k) * ldb + n0 + n] : 0.f;
                sB[n * GKS + k] = f2tf(v);
            }
        }
        __syncthreads();
#pragma unroll
        for (int kk = 0; kk < 4; kk++) {
            const int k8 = kk * 8;
            unsigned a[2][4], b[8][2];
#pragma unroll
            for (int mt = 0; mt < 2; mt++) {
                const unsigned* p = sA + (wm + mt * 16 + gid) * GKS + k8 + tig;
                a[mt][0] = p[0];
                a[mt][1] = p[8 * GKS];
                a[mt][2] = p[4];
                a[mt][3] = p[8 * GKS + 4];
            }
#pragma unroll
            for (int nt = 0; nt < 8; nt++) {
                const unsigned* p = sB + (wn + nt * 8 + gid) * GKS + k8 + tig;
                b[nt][0] = p[0];
                b[nt][1] = p[4];
            }
#pragma unroll
            for (int mt = 0; mt < 2; mt++)
#pragma unroll
                for (int nt = 0; nt < 8; nt++)
                    mma_tf32(acc[mt][nt], a[mt][0], a[mt][1], a[mt][2], a[mt][3],
                             b[nt][0], b[nt][1]);
        }
        __syncthreads();
    }

    float scale = uscale;
    if (gates) scale *= 1.f / (1.f + expf(-gates[z]));
#pragma unroll
    for (int mt = 0; mt < 2; mt++) {
        const int r0 = m0 + wm + mt * 16 + gid;
#pragma unroll
        for (int nt = 0; nt < 8; nt++) {
            const int col = n0 + wn + nt * 8 + tig * 2;
            if (col < N) {
                float bx = 0.f, by = 0.f;
                if (bias) { bx = bias[col]; by = bias[col + 1]; }
                float v00 = (acc[mt][nt][0] + bx) * scale;
                float v01 = (acc[mt][nt][1] + by) * scale;
                float v10 = (acc[mt][nt][2] + bx) * scale;
                float v11 = (acc[mt][nt][3] + by) * scale;
                if (tf32out) {
                    v00 = __uint_as_float(f2tf(v00));
                    v01 = __uint_as_float(f2tf(v01));
                    v10 = __uint_as_float(f2tf(v10));
                    v11 = __uint_as_float(f2tf(v11));
                }
                *(float2*)(C + (long long)r0 * ldc + col)       = make_float2(v00, v01);
                *(float2*)(C + (long long)(r0 + 8) * ldc + col) = make_float2(v10, v11);
            }
        }
    }
}

// ------------------- rmsnorm (in place), optional tf32 round ------------------
__global__ void rmsnorm_kernel(float* __restrict__ data,
                               const float* __restrict__ gamma,
                               int width, int tf32out)
{
    float* p = data + (size_t)blockIdx.x * width;
    const int tid = threadIdx.x;
    float ss = 0.f;
    for (int i = tid * 4; i < width; i += 512) {
        float4 v = *(const float4*)(p + i);
        ss += v.x * v.x + v.y * v.y + v.z * v.z + v.w * v.w;
    }
#pragma unroll
    for (int off = 16; off; off >>= 1) ss += __shfl_xor_sync(~0u, ss, off);
    __shared__ float ws[4];
    if ((tid & 31) == 0) ws[tid >> 5] = ss;
    __syncthreads();
    const float inv = rsqrtf((ws[0] + ws[1] + ws[2] + ws[3]) / (float)width + 1e-6f);
    for (int i = tid * 4; i < width; i += 512) {
        float4 v = *(const float4*)(p + i);
        float4 g = *(const float4*)(gamma + i);
        v.x *= inv * g.x; v.y *= inv * g.y; v.z *= inv * g.z; v.w *= inv * g.w;
        if (tf32out) {
            v.x = __uint_as_float(f2tf(v.x)); v.y = __uint_as_float(f2tf(v.y));
            v.z = __uint_as_float(f2tf(v.z)); v.w = __uint_as_float(f2tf(v.w));
        }
        *(float4*)(p + i) = v;
    }
}

// ------------------- RoPE (in place), tf32-rounded ----------------------------
__device__ __forceinline__ void rope_pair(float* p, int i, int m, float scale)
{
    const float x1 = p[i], x2 = p[i + 32];
    const float pos = (float)(m & (S_ - 1));
    const float inv_freq = exp2f(-(float)i * (13.287712379549449f / 32.f));
    float sn, cs;
    sincosf(pos * inv_freq, &sn, &cs);
    p[i]      = __uint_as_float(f2tf((x1 * cs - x2 * sn) * scale));
    p[i + 32] = __uint_as_float(f2tf((x1 * sn + x2 * cs) * scale));
}

__global__ void rope_q_kernel(float* __restrict__ q)
{
    const int idx = blockIdx.x * 256 + threadIdx.x;
    const int i = idx & 31, rest = idx >> 5;
    const int h = rest & (H_ - 1), m = rest >> 4;
    rope_pair(q + (size_t)m * (H_ * RD_) + h * RD_, i, m, SM_SCALE);
}

__global__ void rope_k_kernel(float* __restrict__ k)
{
    const int idx = blockIdx.x * 256 + threadIdx.x;
    const int i = idx & 31, m = idx >> 5;
    rope_pair(k + (size_t)m * RD_, i, m, 1.f);
}

// ------------------- fused causal flash attention (BM=64, BN=32) --------------
// grid (S/64, H, B), 512 threads (16 warps). Score k192 (absorbed K).
// smem: uQ[64][196], uK[32][196], uV[2][32][520], sP[64][36].
// V double-buffered, prefetched one full tile ahead; K single-buffer,
// prefetched right after score reads it. 4 barriers/tile.
#define QKS 196
#define VST 520
#define PSTR 36
__global__ __launch_bounds__(512, 1) void mla_attn_kernel(
    const float* __restrict__ qnope,  // [MT][H*128] tf32*scale
    const float* __restrict__ qrope,  // [MT][H*64]  tf32*scale
    const float* __restrict__ kabs,   // [H][MT][128] tf32
    const float* __restrict__ krope,  // [MT][64]    tf32
    const float* __restrict__ kvl,    // [MT][512]   tf32
    float* __restrict__ lat)          // [H][MT][512]
{
    extern __shared__ float smf[];
    unsigned* uQ  = (unsigned*)smf;              // 64*196
    unsigned* uK  = uQ + 64 * QKS;               // 32*196
    unsigned* uV  = uK + 32 * QKS;               // 2*32*520
    float* sP     = (float*)(uV + 2 * 32 * VST); // 64*36
    float* sAlpha = sP + 64 * PSTR;              // 64
    float* sL     = sAlpha + 64;                 // 64
    unsigned* uP  = (unsigned*)sP;

    const int qt = blockIdx.x, h = blockIdx.y, b = blockIdx.z;
    const int tid = threadIdx.x;
    const int warp = tid >> 5, lane = tid & 31;
    const int gid = lane >> 2, tig = lane & 3;
    const long long mbase = (long long)b * S_;
    const int q0 = qt * 64;

    // ---- Q tile (64 x 192): cols 0-127 qnope_h, 128-191 qrope_h
    {
        const unsigned* qn = (const unsigned*)qnope + (mbase + q0) * D_ + h * HD_;
#pragma unroll
        for (int i = 0; i < 4; i++) {
            const int idx = tid + i * 512;             // 2048 = 64 rows x 32 u4
            const int r = idx >> 5, cu = idx & 31;
            uint4 v = *(const uint4*)(qn + (long long)r * D_ + cu * 4);
            *(uint4*)(uQ + r * QKS + cu * 4) = v;
        }
        const unsigned* qr = (const unsigned*)qrope + (mbase + q0) * (H_ * RD_) + h * RD_;
#pragma unroll
        for (int i = 0; i < 2; i++) {
            const int idx = tid + i * 512;             // 1024 = 64 x 16 u4
            const int r = idx >> 4, cu = idx & 15;
            uint4 v = *(const uint4*)(qr + (long long)r * (H_ * RD_) + cu * 4);
            *(uint4*)(uQ + r * QKS + 128 + cu * 4) = v;
        }
    }

    const unsigned* kab = (const unsigned*)kabs + ((long long)h * MT + mbase) * HD_;
    const unsigned* krp = (const unsigned*)krope + mbase * RD_;
    const unsigned* kvp = (const unsigned*)kvl + mbase * KL_;

    // roles
    const int m0w = (warp >> 2) * 16, n0w = (warp & 3) * 8;   // score
    const int srow = tid >> 3, scb = (tid & 7) * 4;           // softmax
    const int mg = warp & 3, pc0 = (warp >> 2) * 128;         // PV
    float m_run = -INFINITY, l_run = 0.f;

    float acc[16][4];
#pragma unroll
    for (int nt = 0; nt < 16; nt++)
#pragma unroll
        for (int j = 0; j < 4; j++) acc[nt][j] = 0.f;

    const int ntiles = 2 * qt + 2;

    // prologue: prefetch K_0 (group 1), V_0 -> slot 0 (group 2)
    {
#pragma unroll
        for (int i = 0; i < 2; i++) {
            const int idx = tid + i * 512;             // 1024 = 32 x 32 u4
            const int r = idx >> 5, cu = idx & 31;
            cp16(uK + r * QKS + cu * 4, kab + (long long)r * HD_ + cu * 4);
        }
        {
            const int r = tid >> 4, cu = tid & 15;     // 512 = 32 x 16 u4
            cp16(uK + r * QKS + 128 + cu * 4, krp + (long long)r * RD_ + cu * 4);
        }
        CP_COMMIT();
#pragma unroll
        for (int i = 0; i < 8; i++) {
            const int idx = tid + i * 512;             // 4096 = 32 x 128 u4
            const int r = idx >> 7, cu = idx & 127;
            cp16(uV + r * VST + cu * 4, kvp + (long long)r * KL_ + cu * 4);
        }
        CP_COMMIT();
    }

    for (int tt = 0; tt < ntiles; tt++) {
        const int t0 = tt * 32;
        __syncthreads();                 // prev tile fully done with smem
        // issue V_{tt+1} into slot (tt+1)&1 (full tile ahead)
        {
            const int tn = (tt + 1 < ntiles) ? (tt + 1) * 32 : t0;
            unsigned* dst = uV + ((tt + 1) & 1) * 32 * VST;
#pragma unroll
            for (int i = 0; i < 8; i++) {
                const int idx = tid + i * 512;
                const int r = idx >> 7, cu = idx & 127;
                cp16(dst + r * VST + cu * 4, kvp + (long long)(tn + r) * KL_ + cu * 4);
            }
            CP_COMMIT();
        }
        CP_WAIT1();                      // K_tt and V_tt complete
        __syncthreads();

        // ---- score: warp = m16 x n8 x k192
        float c[4] = {0.f, 0.f, 0.f, 0.f};
        {
            const unsigned* qp0 = uQ + (m0w + gid) * QKS + tig;
            const unsigned* qp1 = qp0 + 8 * QKS;
            const unsigned* kb  = uK + (n0w + gid) * QKS + tig;
#pragma unroll
            for (int kc = 0; kc < 24; kc++) {
                const int k = kc * 8;
                mma_tf32(c, qp0[k], qp1[k], qp0[k + 4], qp1[k + 4],
                         kb[k], kb[k + 4]);
            }
        }
        {
            float* p0 = sP + (m0w + gid) * PSTR + n0w + tig * 2;
            float* p1 = p0 + 8 * PSTR;
            *(float2*)p0 = make_float2(c[0], c[1]);
            *(float2*)p1 = make_float2(c[2], c[3]);
        }
        __syncthreads();                 // scores visible; uK free

        // prefetch K_{tt+1}
        {
            const int tn = (tt + 1 < ntiles) ? (tt + 1) * 32 : t0;
#pragma unroll
            for (int i = 0; i < 2; i++) {
                const int idx = tid + i * 512;
                const int r = idx >> 5, cu = idx & 31;
                cp16(uK + r * QKS + cu * 4, kab + (long long)(tn + r) * HD_ + cu * 4);
            }
            {
                const int r = tid >> 4, cu = tid & 15;
                cp16(uK + r * QKS + 128 + cu * 4, krp + (long long)(tn + r) * RD_ + cu * 4);
            }
            CP_COMMIT();
        }

        // ---- online softmax: 8 thr/row x 4 cols (scale pre-folded into Q)
        {
            const int rglob = q0 + srow;
            float s[4];
            float4 v0 = *(const float4*)&sP[srow * PSTR + scb];
            s[0] = v0.x; s[1] = v0.y; s[2] = v0.z; s[3] = v0.w;
            float mx = -INFINITY;
#pragma unroll
            for (int j = 0; j < 4; j++) {
                if (t0 + scb + j > rglob) s[j] = -INFINITY;
                mx = fmaxf(mx, s[j]);
            }
#pragma unroll
            for (int off = 1; off < 8; off <<= 1)
                mx = fmaxf(mx, __shfl_xor_sync(~0u, mx, off, 8));
            const float mnew = fmaxf(m_run, mx);
            const float alpha = __expf(m_run - mnew);
            float lsum = 0.f;
#pragma unroll
            for (int j = 0; j < 4; j++) { s[j] = __expf(s[j] - mnew); lsum += s[j]; }
#pragma unroll
            for (int off = 1; off < 8; off <<= 1)
                lsum += __shfl_xor_sync(~0u, lsum, off, 8);
            l_run = l_run * alpha + lsum;
            m_run = mnew;
            unsigned* d = uP + srow * PSTR + scb;
#pragma unroll
            for (int j = 0; j < 4; j++) d[j] = f2tf(s[j]);
            if ((tid & 7) == 0) sAlpha[srow] = alpha;
        }
        __syncthreads();                 // P/alpha visible

        // ---- PV: warp = m16 x n128, k=32, V slot tt&1
        {
            const unsigned* uVt = uV + (tt & 1) * 32 * VST;
            const float a0r = sAlpha[mg * 16 + gid];
            const float a1r = sAlpha[mg * 16 + gid + 8];
#pragma unroll
            for (int nt = 0; nt < 16; nt++) {
                acc[nt][0] *= a0r; acc[nt][1] *= a0r;
                acc[nt][2] *= a1r; acc[nt][3] *= a1r;
            }
#pragma unroll
            for (int kc = 0; kc < 4; kc++) {
                const int kk = kc * 8;
                const unsigned* pp = uP + (mg * 16 + gid) * PSTR + kk + tig;
                unsigned pa0 = pp[0];
                unsigned pa1 = pp[8 * PSTR];
                unsigned pa2 = pp[4];
                unsigned pa3 = pp[8 * PSTR + 4];
                const unsigned* v0 = uVt + (kk + tig) * VST + pc0 + gid;
                const unsigned* v1 = v0 + 4 * VST;
#pragma unroll
                for (int nt = 0; nt < 16; nt++)
                    mma_tf32(acc[nt], pa0, pa1, pa2, pa3, v0[nt * 8], v1[nt * 8]);
            }
        }
    }
    CP_WAIT0();

    // ---- epilogue
    if ((tid & 7) == 0) sL[srow] = l_run;
    __syncthreads();
    const float invL = 1.f / sL[mg * 16 + gid];
    const float invH = 1.f / sL[mg * 16 + gid + 8];
    const int rL = mg * 16 + gid, rH = rL + 8;
    float* outp = lat + ((long long)h * MT + mbase + q0) * KL_;
#pragma unroll
    for (int nt = 0; nt < 16; nt++) {
        const int col = pc0 + nt * 8 + tig * 2;
        *(float2*)(outp + (long long)rL * KL_ + col) =
            make_float2(acc[nt][0] * invL, acc[nt][1] * invL);
        *(float2*)(outp + (long long)rH * KL_ + col) =
            make_float2(acc[nt][2] * invH, acc[nt][3] * invH);
    }
}

// ------------------- launch ---------------------------------------------------
extern "C" void kernel_launch(void* const* d_in, const int* in_sizes, int n_in,
                              void* d_out, int out_size)
{
    const float* x      = (const float*)d_in[0];
    const float* w_qd   = (const float*)d_in[3];
    const float* b_qd   = (const float*)d_in[4];
    const float* gam_q  = (const float*)d_in[5];
    const float* w_qn   = (const float*)d_in[6];
    const float* b_qn   = (const float*)d_in[7];
    const float* w_qr   = (const float*)d_in[8];
    const float* b_qr   = (const float*)d_in[9];
    const float* w_kvd  = (const float*)d_in[10];
    const float* b_kvd  = (const float*)d_in[11];
    const float* gam_kv = (const float*)d_in[12];
    const float* w_ku   = (const float*)d_in[13];
    const float* w_vu   = (const float*)d_in[15];
    const float* w_kr   = (const float*)d_in[17];
    const float* b_kr   = (const float*)d_in[18];
    const float* gates  = (const float*)d_in[19];
    const float* w_o    = (const float*)d_in[20];
    const float* b_o    = (const float*)d_in[21];
    float* out = (float*)d_out;

    float *qc, *qnope, *qrope, *kvl, *krope, *kabs, *lat, *outhd;
    cudaGetSymbolAddress((void**)&qc,    g_qc);
    cudaGetSymbolAddress((void**)&qnope, g_qnope);
    cudaGetSymbolAddress((void**)&qrope, g_qrope);
    cudaGetSymbolAddress((void**)&kvl,   g_kvl);
    cudaGetSymbolAddress((void**)&krope, g_krope);
    cudaGetSymbolAddress((void**)&kabs,  g_kabs);
    cudaGetSymbolAddress((void**)&lat,   g_lat);
    cudaGetSymbolAddress((void**)&outhd, g_outhd);

    const int smem_attn = (64 * QKS + 32 * QKS + 2 * 32 * VST + 64 * PSTR + 128)
                          * sizeof(float);
    cudaFuncSetAttribute(mla_attn_kernel,
                         cudaFuncAttributeMaxDynamicSharedMemorySize, smem_attn);

    dim3 blk(256);
    // qc = rmsnorm(x @ w_qd^T + b_qd)
    gemm_tf32<true><<<dim3(QL_ / 128, MT / 128, 1), blk>>>(
        x, D_, 0, w_qd, D_, 0, qc, QL_, 0, QL_, D_, b_qd, nullptr, 1.f, 0);
    rmsnorm_kernel<<<MT, 128>>>(qc, gam_q, QL_, 0);
    // q_nope, scaled + tf32
    gemm_tf32<true><<<dim3(D_ / 128, MT / 128, 1), blk>>>(
        qc, QL_, 0, w_qn, QL_, 0, qnope, D_, 0, D_, QL_, b_qn, nullptr,
        SM_SCALE, 1);
    // q_rope -> rope (scaled, tf32, in place)
    gemm_tf32<true><<<dim3((H_ * RD_) / 128, MT / 128, 1), blk>>>(
        qc, QL_, 0, w_qr, QL_, 0, qrope, H_ * RD_, 0, H_ * RD_, QL_, b_qr, nullptr,
        1.f, 0);
    rope_q_kernel<<<MT * H_ * 32 / 256, 256>>>(qrope);
    // kv latent = rmsnorm(x @ w_kvd^T + b_kvd), tf32
    gemm_tf32<true><<<dim3(KL_ / 128, MT / 128, 1), blk>>>(
        x, D_, 0, w_kvd, D_, 0, kvl, KL_, 0, KL_, D_, b_kvd, nullptr, 1.f, 0);
    rmsnorm_kernel<<<MT, 128>>>(kvl, gam_kv, KL_, 1);
    // k_rope -> rope (tf32, in place)
    gemm_tf32<true><<<dim3(1, MT / 128, 1), blk>>>(
        x, D_, 0, w_kr, D_, 0, krope, RD_, 0, RD_, D_, b_kr, nullptr, 1.f, 0);
    rope_k_kernel<<<MT * 32 / 256, 256>>>(krope);
    // k_abs[h] = kvl @ w_uk[h]^T  (tf32)
    gemm_tf32<true><<<dim3(1, MT / 128, H_), blk>>>(
        kvl, KL_, 0, w_ku, KL_, (long long)HD_ * KL_,
        kabs, HD_, (long long)MT * HD_, HD_, KL_, nullptr, nullptr, 1.f, 1);
    // fused attention
    mla_attn_kernel<<<dim3(S_ / 64, H_, B_), dim3(512), smem_attn>>>(
        qnope, qrope, kabs, krope, kvl, lat);
    // out_h = (lat_h @ w_vu[h]^T) * sigmoid(gate[h])
    gemm_tf32<true><<<dim3(1, MT / 128, H_), blk>>>(
        lat, KL_, (long long)MT * KL_, w_vu, KL_, (long long)HD_ * KL_,
        outhd, D_, HD_, HD_, KL_, nullptr, gates, 1.f, 0);
    // final projection
    gemm_tf32<true><<<dim3(D_ / 128, MT / 128, 1), blk>>>(
        outhd, D_, 0, w_o, D_, 0, out, D_, 0, D_, D_, b_o, nullptr, 1.f, 0);
}

// round 14
// speedup vs baseline: 2.1780x; 1.0852x over previous
#include <cuda_runtime.h>
#include <cuda_bf16.h>
#include <math.h>

#define B_  4
#define S_  2048
#define D_  2048
#define H_  16
#define HD_ 128
#define RD_ 64
#define QL_ 512
#define KL_ 512
#define MT  (B_*S_)
#define SM_SCALE 0.07216878364870323f  // 1/sqrt(192)

// ------------------- scratch (device globals; no runtime allocs) ------------
__device__ float g_qc   [(size_t)MT * QL_];
__device__ float g_qnope[(size_t)MT * D_];          // scaled tf32
__device__ float g_qrope[(size_t)MT * (H_ * RD_)];  // scaled tf32
__device__ float g_kvl  [(size_t)MT * KL_];         // tf32
__device__ float g_krope[(size_t)MT * RD_];         // tf32
__device__ float g_kabs [(size_t)H_ * MT * HD_];    // tf32
__device__ float g_lat  [(size_t)H_ * MT * KL_];
__device__ float g_outhd[(size_t)MT * D_];

// ------------------- tf32 mma helpers ----------------------------------------
__device__ __forceinline__ unsigned f2tf(float f)
{
    unsigned u; asm("cvt.rna.tf32.f32 %0, %1;" : "=r"(u) : "f"(f)); return u;
}
__device__ __forceinline__ void mma_tf32(float c[4],
    unsigned a0, unsigned a1, unsigned a2, unsigned a3,
    unsigned b0, unsigned b1)
{
    asm volatile("mma.sync.aligned.m16n8k8.row.col.f32.tf32.tf32.f32 "
                 "{%0,%1,%2,%3},{%4,%5,%6,%7},{%8,%9},{%0,%1,%2,%3};"
                 : "+f"(c[0]), "+f"(c[1]), "+f"(c[2]), "+f"(c[3])
                 : "r"(a0), "r"(a1), "r"(a2), "r"(a3), "r"(b0), "r"(b1));
}
__device__ __forceinline__ void cp16(void* smem, const void* gmem)
{
    unsigned s = (unsigned)__cvta_generic_to_shared(smem);
    asm volatile("cp.async.cg.shared.global [%0], [%1], 16;\n" :: "r"(s), "l"(gmem));
}
#define CP_COMMIT() asm volatile("cp.async.commit_group;\n" ::: "memory")
#define CP_WAIT1()  asm volatile("cp.async.wait_group 1;\n" ::: "memory")
#define CP_WAIT0()  asm volatile("cp.async.wait_group 0;\n" ::: "memory")

// ------------------- tf32 tensor-core GEMM (projections) ----------------------
#define GKS 36
template<bool TRANSB>
__global__ __launch_bounds__(256) void gemm_tf32(
    const float* __restrict__ A, int lda, long long sAz,
    const float* __restrict__ B, int ldb, long long sBz,
    float* __restrict__ C, int ldc, long long sCz,
    int N, int K,
    const float* __restrict__ bias,
    const float* __restrict__ gates,
    float uscale, int tf32out)
{
    __shared__ unsigned sA[128 * GKS];
    __shared__ unsigned sB[128 * GKS];

    const int z = blockIdx.z;
    A += (long long)z * sAz;  B += (long long)z * sBz;  C += (long long)z * sCz;

    const int tid = threadIdx.x;
    const int warp = tid >> 5, lane = tid & 31;
    const int gid = lane >> 2, tig = lane & 3;
    const int m0 = blockIdx.y * 128, n0 = blockIdx.x * 128;
    const int wm = (warp & 3) * 32;
    const int wn = (warp >> 2) * 64;

    float acc[2][8][4];
#pragma unroll
    for (int mt = 0; mt < 2; mt++)
#pragma unroll
        for (int nt = 0; nt < 8; nt++)
#pragma unroll
            for (int j = 0; j < 4; j++) acc[mt][nt][j] = 0.f;

    for (int k0 = 0; k0 < K; k0 += 32) {
#pragma unroll
        for (int i = 0; i < 4; i++) {
            const int lin = tid + i * 256;
            const int r = lin >> 3, c4 = (lin & 7) * 4;
            float4 v = *(const float4*)(A + (long long)(m0 + r) * lda + k0 + c4);
            unsigned* d = sA + r * GKS + c4;
            d[0] = f2tf(v.x); d[1] = f2tf(v.y); d[2] = f2tf(v.z); d[3] = f2tf(v.w);
        }
        if (TRANSB) {
#pragma unroll
            for (int i = 0; i < 4; i++) {
                const int lin = tid + i * 256;
                const int r = lin >> 3, c4 = (lin & 7) * 4;
                float4 v = make_float4(0.f, 0.f, 0.f, 0.f);
                if (n0 + r < N)
                    v = *(const float4*)(B + (long long)(n0 + r) * ldb + k0 + c4);
                unsigned* d = sB + r * GKS + c4;
                d[0] = f2tf(v.x); d[1] = f2tf(v.y); d[2] = f2tf(v.z); d[3] = f2tf(v.w);
            }
        } else {
#pragma unroll
            for (int i = 0; i < 16; i++) {
                const int lin = tid + i * 256;
                const int n = lin & 127, k = lin >> 7;
                float v = (n0 + n < N) ? B[(long long)(k0 + k) * ldb + n0 + n] : 0.f;
                sB[n * GKS + k] = f2tf(v);
            }
        }
        __syncthreads();
#pragma unroll
        for (int kk = 0; kk < 4; kk++) {
            const int k8 = kk * 8;
            unsigned a[2][4], b[8][2];
#pragma unroll
            for (int mt = 0; mt < 2; mt++) {
                const unsigned* p = sA + (wm + mt * 16 + gid) * GKS + k8 + tig;
                a[mt][0] = p[0];
                a[mt][1] = p[8 * GKS];
                a[mt][2] = p[4];
                a[mt][3] = p[8 * GKS + 4];
            }
#pragma unroll
            for (int nt = 0; nt < 8; nt++) {
                const unsigned* p = sB + (wn + nt * 8 + gid) * GKS + k8 + tig;
                b[nt][0] = p[0];
                b[nt][1] = p[4];
            }
#pragma unroll
            for (int mt = 0; mt < 2; mt++)
#pragma unroll
                for (int nt = 0; nt < 8; nt++)
                    mma_tf32(acc[mt][nt], a[mt][0], a[mt][1], a[mt][2], a[mt][3],
                             b[nt][0], b[nt][1]);
        }
        __syncthreads();
    }

    float scale = uscale;
    if (gates) scale *= 1.f / (1.f + expf(-gates[z]));
#pragma unroll
    for (int mt = 0; mt < 2; mt++) {
        const int r0 = m0 + wm + mt * 16 + gid;
#pragma unroll
        for (int nt = 0; nt < 8; nt++) {
            const int col = n0 + wn + nt * 8 + tig * 2;
            if (col < N) {
                float bx = 0.f, by = 0.f;
                if (bias) { bx = bias[col]; by = bias[col + 1]; }
                float v00 = (acc[mt][nt][0] + bx) * scale;
                float v01 = (acc[mt][nt][1] + by) * scale;
                float v10 = (acc[mt][nt][2] + bx) * scale;
                float v11 = (acc[mt][nt][3] + by) * scale;
                if (tf32out) {
                    v00 = __uint_as_float(f2tf(v00));
                    v01 = __uint_as_float(f2tf(v01));
                    v10 = __uint_as_float(f2tf(v10));
                    v11 = __uint_as_float(f2tf(v11));
                }
                *(float2*)(C + (long long)r0 * ldc + col)       = make_float2(v00, v01);
                *(float2*)(C + (long long)(r0 + 8) * ldc + col) = make_float2(v10, v11);
            }
        }
    }
}

// ------------------- rmsnorm (in place), optional tf32 round ------------------
__global__ void rmsnorm_kernel(float* __restrict__ data,
                               const float* __restrict__ gamma,
                               int width, int tf32out)
{
    float* p = data + (size_t)blockIdx.x * width;
    const int tid = threadIdx.x;
    float ss = 0.f;
    for (int i = tid * 4; i < width; i += 512) {
        float4 v = *(const float4*)(p + i);
        ss += v.x * v.x + v.y * v.y + v.z * v.z + v.w * v.w;
    }
#pragma unroll
    for (int off = 16; off; off >>= 1) ss += __shfl_xor_sync(~0u, ss, off);
    __shared__ float ws[4];
    if ((tid & 31) == 0) ws[tid >> 5] = ss;
    __syncthreads();
    const float inv = rsqrtf((ws[0] + ws[1] + ws[2] + ws[3]) / (float)width + 1e-6f);
    for (int i = tid * 4; i < width; i += 512) {
        float4 v = *(const float4*)(p + i);
        float4 g = *(const float4*)(gamma + i);
        v.x *= inv * g.x; v.y *= inv * g.y; v.z *= inv * g.z; v.w *= inv * g.w;
        if (tf32out) {
            v.x = __uint_as_float(f2tf(v.x)); v.y = __uint_as_float(f2tf(v.y));
            v.z = __uint_as_float(f2tf(v.z)); v.w = __uint_as_float(f2tf(v.w));
        }
        *(float4*)(p + i) = v;
    }
}

// ------------------- RoPE (in place), tf32-rounded ----------------------------
__device__ __forceinline__ void rope_pair(float* p, int i, int m, float scale)
{
    const float x1 = p[i], x2 = p[i + 32];
    const float pos = (float)(m & (S_ - 1));
    const float inv_freq = exp2f(-(float)i * (13.287712379549449f / 32.f));
    float sn, cs;
    sincosf(pos * inv_freq, &sn, &cs);
    p[i]      = __uint_as_float(f2tf((x1 * cs - x2 * sn) * scale));
    p[i + 32] = __uint_as_float(f2tf((x1 * sn + x2 * cs) * scale));
}

__global__ void rope_q_kernel(float* __restrict__ q)
{
    const int idx = blockIdx.x * 256 + threadIdx.x;
    const int i = idx & 31, rest = idx >> 5;
    const int h = rest & (H_ - 1), m = rest >> 4;
    rope_pair(q + (size_t)m * (H_ * RD_) + h * RD_, i, m, SM_SCALE);
}

__global__ void rope_k_kernel(float* __restrict__ k)
{
    const int idx = blockIdx.x * 256 + threadIdx.x;
    const int i = idx & 31, m = idx >> 5;
    rope_pair(k + (size_t)m * RD_, i, m, 1.f);
}

// ------------------- fused causal flash attention (BM=64, BN=32) --------------
// grid (S/64, H, B), 512 threads (16 warps). Score k192 (absorbed K).
// smem: uQ[64][196], uK[32][196], uV[2][32][520], sP[64][36].
// Score: warps 0-7, each m16 x n16 x full k192 (4 LDS/mma).
// PV:    all warps, m32 x n64 (1.5 LDS/mma).
// V double-buffered, one tile ahead; K prefetched after score reads it.
#define QKS 196
#define VST 520
#define PSTR 36
__global__ __launch_bounds__(512, 1) void mla_attn_kernel(
    const float* __restrict__ qnope,  // [MT][H*128] tf32*scale
    const float* __restrict__ qrope,  // [MT][H*64]  tf32*scale
    const float* __restrict__ kabs,   // [H][MT][128] tf32
    const float* __restrict__ krope,  // [MT][64]    tf32
    const float* __restrict__ kvl,    // [MT][512]   tf32
    float* __restrict__ lat)          // [H][MT][512]
{
    extern __shared__ float smf[];
    unsigned* uQ  = (unsigned*)smf;              // 64*196
    unsigned* uK  = uQ + 64 * QKS;               // 32*196
    unsigned* uV  = uK + 32 * QKS;               // 2*32*520
    float* sP     = (float*)(uV + 2 * 32 * VST); // 64*36
    float* sAlpha = sP + 64 * PSTR;              // 64
    float* sL     = sAlpha + 64;                 // 64
    unsigned* uP  = (unsigned*)sP;

    const int qt = blockIdx.x, h = blockIdx.y, b = blockIdx.z;
    const int tid = threadIdx.x;
    const int warp = tid >> 5, lane = tid & 31;
    const int gid = lane >> 2, tig = lane & 3;
    const long long mbase = (long long)b * S_;
    const int q0 = qt * 64;

    // ---- Q tile (64 x 192): cols 0-127 qnope_h, 128-191 qrope_h
    {
        const unsigned* qn = (const unsigned*)qnope + (mbase + q0) * D_ + h * HD_;
#pragma unroll
        for (int i = 0; i < 4; i++) {
            const int idx = tid + i * 512;             // 2048 = 64 rows x 32 u4
            const int r = idx >> 5, cu = idx & 31;
            uint4 v = *(const uint4*)(qn + (long long)r * D_ + cu * 4);
            *(uint4*)(uQ + r * QKS + cu * 4) = v;
        }
        const unsigned* qr = (const unsigned*)qrope + (mbase + q0) * (H_ * RD_) + h * RD_;
#pragma unroll
        for (int i = 0; i < 2; i++) {
            const int idx = tid + i * 512;             // 1024 = 64 x 16 u4
            const int r = idx >> 4, cu = idx & 15;
            uint4 v = *(const uint4*)(qr + (long long)r * (H_ * RD_) + cu * 4);
            *(uint4*)(uQ + r * QKS + 128 + cu * 4) = v;
        }
    }

    const unsigned* kab = (const unsigned*)kabs + ((long long)h * MT + mbase) * HD_;
    const unsigned* krp = (const unsigned*)krope + mbase * RD_;
    const unsigned* kvp = (const unsigned*)kvl + mbase * KL_;

    // roles
    const int sm0 = (warp >> 1) * 16, sn0 = (warp & 1) * 16;  // score (warps 0-7)
    const int srow = tid >> 3, scb = (tid & 7) * 4;           // softmax
    const int pm = (warp >> 3) * 32, pn = (warp & 7) * 64;    // PV
    float m_run = -INFINITY, l_run = 0.f;

    float acc[2][8][4];
#pragma unroll
    for (int ms = 0; ms < 2; ms++)
#pragma unroll
        for (int nt = 0; nt < 8; nt++)
#pragma unroll
            for (int j = 0; j < 4; j++) acc[ms][nt][j] = 0.f;

    const int ntiles = 2 * qt + 2;

    // prologue: prefetch K_0 (group 1), V_0 -> slot 0 (group 2)
    {
#pragma unroll
        for (int i = 0; i < 2; i++) {
            const int idx = tid + i * 512;             // 1024 = 32 x 32 u4
            const int r = idx >> 5, cu = idx & 31;
            cp16(uK + r * QKS + cu * 4, kab + (long long)r * HD_ + cu * 4);
        }
        {
            const int r = tid >> 4, cu = tid & 15;     // 512 = 32 x 16 u4
            cp16(uK + r * QKS + 128 + cu * 4, krp + (long long)r * RD_ + cu * 4);
        }
        CP_COMMIT();
#pragma unroll
        for (int i = 0; i < 8; i++) {
            const int idx = tid + i * 512;             // 4096 = 32 x 128 u4
            const int r = idx >> 7, cu = idx & 127;
            cp16(uV + r * VST + cu * 4, kvp + (long long)r * KL_ + cu * 4);
        }
        CP_COMMIT();
    }

    for (int tt = 0; tt < ntiles; tt++) {
        const int t0 = tt * 32;
        __syncthreads();                 // prev tile fully done with smem
        // issue V_{tt+1} into slot (tt+1)&1 (full tile ahead)
        {
            const int tn = (tt + 1 < ntiles) ? (tt + 1) * 32 : t0;
            unsigned* dst = uV + ((tt + 1) & 1) * 32 * VST;
#pragma unroll
            for (int i = 0; i < 8; i++) {
                const int idx = tid + i * 512;
                const int r = idx >> 7, cu = idx & 127;
                cp16(dst + r * VST + cu * 4, kvp + (long long)(tn + r) * KL_ + cu * 4);
            }
            CP_COMMIT();
        }
        CP_WAIT1();                      // K_tt and V_tt complete
        __syncthreads();

        // ---- score: warps 0-7, each m16 x n16 x k192
        if (warp < 8) {
            float c0[4] = {0.f, 0.f, 0.f, 0.f}, c1[4] = {0.f, 0.f, 0.f, 0.f};
            const unsigned* qp0 = uQ + (sm0 + gid) * QKS + tig;
            const unsigned* qp1 = qp0 + 8 * QKS;
            const unsigned* kb0 = uK + (sn0 + gid) * QKS + tig;
            const unsigned* kb1 = kb0 + 8 * QKS;
#pragma unroll
            for (int kc = 0; kc < 24; kc++) {
                const int k = kc * 8;
                unsigned a0 = qp0[k], a1 = qp1[k], a2 = qp0[k + 4], a3 = qp1[k + 4];
                mma_tf32(c0, a0, a1, a2, a3, kb0[k], kb0[k + 4]);
                mma_tf32(c1, a0, a1, a2, a3, kb1[k], kb1[k + 4]);
            }
            float* p0 = sP + (sm0 + gid) * PSTR + sn0 + tig * 2;
            float* p1 = p0 + 8 * PSTR;
            *(float2*)p0       = make_float2(c0[0], c0[1]);
            *(float2*)p1       = make_float2(c0[2], c0[3]);
            *(float2*)(p0 + 8) = make_float2(c1[0], c1[1]);
            *(float2*)(p1 + 8) = make_float2(c1[2], c1[3]);
        }
        __syncthreads();                 // scores visible; uK free

        // prefetch K_{tt+1}
        {
            const int tn = (tt + 1 < ntiles) ? (tt + 1) * 32 : t0;
#pragma unroll
            for (int i = 0; i < 2; i++) {
                const int idx = tid + i * 512;
                const int r = idx >> 5, cu = idx & 31;
                cp16(uK + r * QKS + cu * 4, kab + (long long)(tn + r) * HD_ + cu * 4);
            }
            {
                const int r = tid >> 4, cu = tid & 15;
                cp16(uK + r * QKS + 128 + cu * 4, krp + (long long)(tn + r) * RD_ + cu * 4);
            }
            CP_COMMIT();
        }

        // ---- online softmax: 8 thr/row x 4 cols (scale pre-folded into Q)
        {
            const int rglob = q0 + srow;
            float s[4];
            float4 v0 = *(const float4*)&sP[srow * PSTR + scb];
            s[0] = v0.x; s[1] = v0.y; s[2] = v0.z; s[3] = v0.w;
            float mx = -INFINITY;
#pragma unroll
            for (int j = 0; j < 4; j++) {
                if (t0 + scb + j > rglob) s[j] = -INFINITY;
                mx = fmaxf(mx, s[j]);
            }
#pragma unroll
            for (int off = 1; off < 8; off <<= 1)
                mx = fmaxf(mx, __shfl_xor_sync(~0u, mx, off, 8));
            const float mnew = fmaxf(m_run, mx);
            const float alpha = __expf(m_run - mnew);
            float lsum = 0.f;
#pragma unroll
            for (int j = 0; j < 4; j++) { s[j] = __expf(s[j] - mnew); lsum += s[j]; }
#pragma unroll
            for (int off = 1; off < 8; off <<= 1)
                lsum += __shfl_xor_sync(~0u, lsum, off, 8);
            l_run = l_run * alpha + lsum;
            m_run = mnew;
            unsigned* d = uP + srow * PSTR + scb;
#pragma unroll
            for (int j = 0; j < 4; j++) d[j] = f2tf(s[j]);
            if ((tid & 7) == 0) sAlpha[srow] = alpha;
        }
        __syncthreads();                 // P/alpha visible

        // ---- PV: warp = m32 x n64, k=32, V slot tt&1
        {
            const unsigned* uVt = uV + (tt & 1) * 32 * VST;
            float aL[2], aH[2];
            aL[0] = sAlpha[pm + gid];       aH[0] = sAlpha[pm + gid + 8];
            aL[1] = sAlpha[pm + 16 + gid];  aH[1] = sAlpha[pm + 16 + gid + 8];
#pragma unroll
            for (int ms = 0; ms < 2; ms++)
#pragma unroll
                for (int nt = 0; nt < 8; nt++) {
                    acc[ms][nt][0] *= aL[ms]; acc[ms][nt][1] *= aL[ms];
                    acc[ms][nt][2] *= aH[ms]; acc[ms][nt][3] *= aH[ms];
                }
#pragma unroll
            for (int kc = 0; kc < 4; kc++) {
                const int kk = kc * 8;
                unsigned pa[2][4];
#pragma unroll
                for (int ms = 0; ms < 2; ms++) {
                    const unsigned* pp = uP + (pm + ms * 16 + gid) * PSTR + kk + tig;
                    pa[ms][0] = pp[0];
                    pa[ms][1] = pp[8 * PSTR];
                    pa[ms][2] = pp[4];
                    pa[ms][3] = pp[8 * PSTR + 4];
                }
                const unsigned* v0 = uVt + (kk + tig) * VST + pn + gid;
                const unsigned* v1 = v0 + 4 * VST;
#pragma unroll
                for (int nt = 0; nt < 8; nt++) {
                    unsigned b0 = v0[nt * 8], b1 = v1[nt * 8];
                    mma_tf32(acc[0][nt], pa[0][0], pa[0][1], pa[0][2], pa[0][3], b0, b1);
                    mma_tf32(acc[1][nt], pa[1][0], pa[1][1], pa[1][2], pa[1][3], b0, b1);
                }
            }
        }
    }
    CP_WAIT0();

    // ---- epilogue
    if ((tid & 7) == 0) sL[srow] = l_run;
    __syncthreads();
    float* outp = lat + ((long long)h * MT + mbase + q0) * KL_;
#pragma unroll
    for (int ms = 0; ms < 2; ms++) {
        const int rL = pm + ms * 16 + gid, rH = rL + 8;
        const float invL = 1.f / sL[rL];
        const float invH = 1.f / sL[rH];
#pragma unroll
        for (int nt = 0; nt < 8; nt++) {
            const int col = pn + nt * 8 + tig * 2;
            *(float2*)(outp + (long long)rL * KL_ + col) =
                make_float2(acc[ms][nt][0] * invL, acc[ms][nt][1] * invL);
            *(float2*)(outp + (long long)rH * KL_ + col) =
                make_float2(acc[ms][nt][2] * invH, acc[ms][nt][3] * invH);
        }
    }
}

// ------------------- launch ---------------------------------------------------
extern "C" void kernel_launch(void* const* d_in, const int* in_sizes, int n_in,
                              void* d_out, int out_size)
{
    const float* x      = (const float*)d_in[0];
    const float* w_qd   = (const float*)d_in[3];
    const float* b_qd   = (const float*)d_in[4];
    const float* gam_q  = (const float*)d_in[5];
    const float* w_qn   = (const float*)d_in[6];
    const float* b_qn   = (const float*)d_in[7];
    const float* w_qr   = (const float*)d_in[8];
    const float* b_qr   = (const float*)d_in[9];
    const float* w_kvd  = (const float*)d_in[10];
    const float* b_kvd  = (const float*)d_in[11];
    const float* gam_kv = (const float*)d_in[12];
    const float* w_ku   = (const float*)d_in[13];
    const float* w_vu   = (const float*)d_in[15];
    const float* w_kr   = (const float*)d_in[17];
    const float* b_kr   = (const float*)d_in[18];
    const float* gates  = (const float*)d_in[19];
    const float* w_o    = (const float*)d_in[20];
    const float* b_o    = (const float*)d_in[21];
    float* out = (float*)d_out;

    float *qc, *qnope, *qrope, *kvl, *krope, *kabs, *lat, *outhd;
    cudaGetSymbolAddress((void**)&qc,    g_qc);
    cudaGetSymbolAddress((void**)&qnope, g_qnope);
    cudaGetSymbolAddress((void**)&qrope, g_qrope);
    cudaGetSymbolAddress((void**)&kvl,   g_kvl);
    cudaGetSymbolAddress((void**)&krope, g_krope);
    cudaGetSymbolAddress((void**)&kabs,  g_kabs);
    cudaGetSymbolAddress((void**)&lat,   g_lat);
    cudaGetSymbolAddress((void**)&outhd, g_outhd);

    const int smem_attn = (64 * QKS + 32 * QKS + 2 * 32 * VST + 64 * PSTR + 128)
                          * sizeof(float);
    cudaFuncSetAttribute(mla_attn_kernel,
                         cudaFuncAttributeMaxDynamicSharedMemorySize, smem_attn);

    dim3 blk(256);
    // qc = rmsnorm(x @ w_qd^T + b_qd)
    gemm_tf32<true><<<dim3(QL_ / 128, MT / 128, 1), blk>>>(
        x, D_, 0, w_qd, D_, 0, qc, QL_, 0, QL_, D_, b_qd, nullptr, 1.f, 0);
    rmsnorm_kernel<<<MT, 128>>>(qc, gam_q, QL_, 0);
    // q_nope, scaled + tf32
    gemm_tf32<true><<<dim3(D_ / 128, MT / 128, 1), blk>>>(
        qc, QL_, 0, w_qn, QL_, 0, qnope, D_, 0, D_, QL_, b_qn, nullptr,
        SM_SCALE, 1);
    // q_rope -> rope (scaled, tf32, in place)
    gemm_tf32<true><<<dim3((H_ * RD_) / 128, MT / 128, 1), blk>>>(
        qc, QL_, 0, w_qr, QL_, 0, qrope, H_ * RD_, 0, H_ * RD_, QL_, b_qr, nullptr,
        1.f, 0);
    rope_q_kernel<<<MT * H_ * 32 / 256, 256>>>(qrope);
    // kv latent = rmsnorm(x @ w_kvd^T + b_kvd), tf32
    gemm_tf32<true><<<dim3(KL_ / 128, MT / 128, 1), blk>>>(
        x, D_, 0, w_kvd, D_, 0, kvl, KL_, 0, KL_, D_, b_kvd, nullptr, 1.f, 0);
    rmsnorm_kernel<<<MT, 128>>>(kvl, gam_kv, KL_, 1);
    // k_rope -> rope (tf32, in place)
    gemm_tf32<true><<<dim3(1, MT / 128, 1), blk>>>(
        x, D_, 0, w_kr, D_, 0, krope, RD_, 0, RD_, D_, b_kr, nullptr, 1.f, 0);
    rope_k_kernel<<<MT * 32 / 256, 256>>>(krope);
    // k_abs[h] = kvl @ w_uk[h]^T  (tf32)
    gemm_tf32<true><<<dim3(1, MT / 128, H_), blk>>>(
        kvl, KL_, 0, w_ku, KL_, (long long)HD_ * KL_,
        kabs, HD_, (long long)MT * HD_, HD_, KL_, nullptr, nullptr, 1.f, 1);
    // fused attention
    mla_attn_kernel<<<dim3(S_ / 64, H_, B_), dim3(512), smem_attn>>>(
        qnope, qrope, kabs, krope, kvl, lat);
    // out_h = (lat_h @ w_vu[h]^T) * sigmoid(gate[h])
    gemm_tf32<true><<<dim3(1, MT / 128, H_), blk>>>(
        lat, KL_, (long long)MT * KL_, w_vu, KL_, (long long)HD_ * KL_,
        outhd, D_, HD_, HD_, KL_, nullptr, gates, 1.f, 0);
    // final projection
    gemm_tf32<true><<<dim3(D_ / 128, MT / 128, 1), blk>>>(
        outhd, D_, 0, w_o, D_, 0, out, D_, 0, D_, D_, b_o, nullptr, 1.f, 0);
}